// round 1
// baseline (speedup 1.0000x reference)
#include <cuda_runtime.h>
#include <math.h>

#define B   32
#define NF  128
#define DE  256
#define DH  512
#define G   2
#define SL  8

// ---- device scratch (no allocations allowed) ----
__device__ float g_query[B * DE];
__device__ float g_attin[B * NF * G];
__device__ float g_bufA[B * NF * NF];
__device__ float g_bufB[B * NF * NF];
__device__ float g_final[B * NF * NF];
__device__ float g_attout[B * NF * G];

// ============================================================================
// Kernel 1: query = c_i @ W^T + b, and att_in = einsum('bngs,bs->bng')
// grid(B), block(256)
// ============================================================================
__global__ __launch_bounds__(256) void query_kernel(
    const float* __restrict__ c_i, const float* __restrict__ W,
    const float* __restrict__ bias,
    const float* __restrict__ att_stack, const float* __restrict__ stack_ptr)
{
    int b = blockIdx.x;
    int t = threadIdx.x;
    __shared__ float csh[DH];
    csh[t]       = c_i[b * DH + t];
    csh[t + 256] = c_i[b * DH + t + 256];
    __syncthreads();

    int w = t >> 5, lane = t & 31;
    // warp per output row of W (DE rows), coalesced lane-strided loads
    for (int d = w; d < DE; d += 8) {
        const float* Wr = W + (size_t)d * DH;
        float s = 0.f;
        #pragma unroll
        for (int i = 0; i < DH / 32; i++)
            s += Wr[lane + 32 * i] * csh[lane + 32 * i];
        #pragma unroll
        for (int o = 16; o; o >>= 1) s += __shfl_xor_sync(~0u, s, o);
        if (lane == 0) g_query[b * DE + d] = s + bias[d];
    }

    // att_in[b,n,g] = sum_s att_stack[b,n,g,s] * stack_ptr[b,s]
    {
        int n = t >> 1, g = t & 1;
        const float* as = att_stack + (((size_t)b * NF + n) * G + g) * SL;
        const float* sp = stack_ptr + b * SL;
        float s = 0.f;
        #pragma unroll
        for (int ss = 0; ss < SL; ss++) s += as[ss] * sp[ss];
        g_attin[(b * NF + n) * G + g] = s;
    }
}

// ============================================================================
// Kernel 2: mask power step.  next = (cur @ M) * 0.9 ; final (+)= next
// step 0: cur=relmask -> bufA, final = M + next
// step 1: cur=bufA    -> bufB, final += next
// step 2: cur=bufB    -> bufA, final += next
// grid(8, B), block(128). 16 output rows per block, 4x4 register tile/thread.
// ============================================================================
__global__ __launch_bounds__(128) void maskpow_kernel(
    const float* __restrict__ relmask, int step)
{
    int b  = blockIdx.y;
    int n0 = blockIdx.x * 16;
    const float* Mb = relmask + (size_t)b * NF * NF;
    const float* cb = (step == 0 ? relmask : (step == 1 ? (const float*)g_bufA
                                                        : (const float*)g_bufB))
                      + (size_t)b * NF * NF;
    float* outb = (step == 1 ? g_bufB : g_bufA) + (size_t)b * NF * NF;
    float* fin  = g_final + (size_t)b * NF * NF;

    __shared__ float csh[16][NF];
    __shared__ float msh[32][NF];
    int t = threadIdx.x;

    for (int i = t; i < 16 * NF; i += 128)
        csh[i >> 7][i & 127] = cb[(size_t)(n0 + (i >> 7)) * NF + (i & 127)];

    float acc[4][4] = {};
    int tn = (t >> 5) * 4;
    int tm = (t & 31) * 4;

    for (int kt = 0; kt < 4; kt++) {
        __syncthreads();
        for (int i = t; i < 32 * NF; i += 128)
            msh[i >> 7][i & 127] = Mb[(size_t)(kt * 32 + (i >> 7)) * NF + (i & 127)];
        __syncthreads();
        #pragma unroll 8
        for (int kk = 0; kk < 32; kk++) {
            float4 mv = *(const float4*)&msh[kk][tm];
            #pragma unroll
            for (int i = 0; i < 4; i++) {
                float c = csh[tn + i][kt * 32 + kk];
                acc[i][0] += c * mv.x; acc[i][1] += c * mv.y;
                acc[i][2] += c * mv.z; acc[i][3] += c * mv.w;
            }
        }
    }

    #pragma unroll
    for (int i = 0; i < 4; i++) {
        int n = n0 + tn + i;
        size_t base = (size_t)n * NF + tm;
        float4 v;
        v.x = 0.9f * acc[i][0]; v.y = 0.9f * acc[i][1];
        v.z = 0.9f * acc[i][2]; v.w = 0.9f * acc[i][3];
        *(float4*)&outb[base] = v;
        float4 f;
        if (step == 0) {
            float4 mm = *(const float4*)&Mb[base];
            f.x = mm.x + v.x; f.y = mm.y + v.y; f.z = mm.z + v.z; f.w = mm.w + v.w;
        } else {
            float4 pf = *(const float4*)&fin[base];
            f.x = pf.x + v.x; f.y = pf.y + v.y; f.z = pf.z + v.z; f.w = pf.w + v.w;
        }
        *(float4*)&fin[base] = f;
    }
}

// ============================================================================
// Kernel 3: main stream.  Block = (b, m).  For all n:
//   weit = sigmoid(feat_edge[b,n,m,:] . query[b,:]) * final_mask[b,n,m]
//   att_out[b,m,g] += att_in[b,n,g] * weit        (block-local, no atomics)
// grid(B*NF), block(256) = 8 warps, warp handles 16 n's.
// ============================================================================
__global__ __launch_bounds__(256) void main_kernel(const float* __restrict__ fe)
{
    int bid = blockIdx.x;
    int b = bid >> 7;
    int m = bid & 127;
    __shared__ float qsh[DE];
    __shared__ float ash[NF * G];
    __shared__ float msk[NF];
    __shared__ float part[8][2];

    int t = threadIdx.x;
    qsh[t] = g_query[b * DE + t];
    ash[t] = g_attin[b * NF * G + t];
    if (t < NF) msk[t] = g_final[((size_t)b * NF + t) * NF + m];
    __syncthreads();

    int w = t >> 5, lane = t & 31;
    float4 q1 = *(const float4*)&qsh[lane * 4];
    float4 q2 = *(const float4*)&qsh[128 + lane * 4];
    const float* febase = fe + (((size_t)b * NF) * NF + m) * DE;

    float p0 = 0.f, p1 = 0.f;
    #pragma unroll 2
    for (int j = 0; j < 16; j++) {
        int n = w + 8 * j;
        float mk = msk[n];
        if (mk != 0.f) {
            const float4* row = (const float4*)(febase + (size_t)n * NF * DE);
            float4 v1 = row[lane];
            float4 v2 = row[lane + 32];
            float s = v1.x * q1.x + v1.y * q1.y + v1.z * q1.z + v1.w * q1.w
                    + v2.x * q2.x + v2.y * q2.y + v2.z * q2.z + v2.w * q2.w;
            #pragma unroll
            for (int o = 16; o; o >>= 1) s += __shfl_xor_sync(~0u, s, o);
            float wv = mk / (1.f + __expf(-s));
            p0 += ash[n * 2]     * wv;
            p1 += ash[n * 2 + 1] * wv;
        }
    }
    if (lane == 0) { part[w][0] = p0; part[w][1] = p1; }
    __syncthreads();
    if (t < 2) {
        float s = 0.f;
        #pragma unroll
        for (int i = 0; i < 8; i++) s += part[i][t];
        g_attout[((size_t)b * NF + m) * G + t] = s;
    }
}

// ============================================================================
// Kernel 4: normalize + blend + write all four outputs.
// grid(B), block(256)
// ============================================================================
__global__ __launch_bounds__(256) void finalize_kernel(
    const float* __restrict__ att_stack, const float* __restrict__ stack_ptr,
    float* __restrict__ out)
{
    int b = blockIdx.x;
    int t = threadIdx.x;
    __shared__ float att[NF * G];
    __shared__ float norm[G];
    __shared__ float sps[SL];

    att[t] = g_attout[b * NF * G + t];
    if (t < SL) sps[t] = stack_ptr[b * SL + t];
    __syncthreads();

    if (t < 64) {
        int g = t >> 5, lane = t & 31;
        float mx = -1e30f;
        for (int i = lane; i < NF; i += 32) mx = fmaxf(mx, att[i * G + g]);
        #pragma unroll
        for (int o = 16; o; o >>= 1) mx = fmaxf(mx, __shfl_xor_sync(~0u, mx, o));
        if (lane == 0) norm[g] = (mx <= 1.f) ? 1.f : mx;
    }
    __syncthreads();

    // output 0: att_stack_new  (B,NF,G,SL)
    const float* asb = att_stack + (size_t)b * NF * G * SL;
    float* ob = out + (size_t)b * NF * G * SL;
    for (int idx = t; idx < NF * G * SL; idx += 256) {
        int s = idx & 7;
        int g = (idx >> 3) & 1;
        int n = idx >> 4;
        float a  = att[n * G + g] / norm[g];
        float sp = sps[s];
        ob[idx] = a * sp + asb[idx] * (1.f - sp);
    }
    // output 1: stack_ptr copy
    if (t < SL) out[(size_t)B * NF * G * SL + b * SL + t] = sps[t];
    // outputs 2 & 3: zeros (B,DH) each
    float* z = out + (size_t)B * NF * G * SL + (size_t)B * SL;
    for (int i = t; i < DH; i += 256) {
        z[(size_t)b * DH + i] = 0.f;
        z[(size_t)B * DH + (size_t)b * DH + i] = 0.f;
    }
}

// ============================================================================
extern "C" void kernel_launch(void* const* d_in, const int* in_sizes, int n_in,
                              void* d_out, int out_size)
{
    // metadata order: vision_feat, feat, feat_edge, c_i, relation_mask,
    //                 att_stack, stack_ptr, mem_in, map_c_w, map_c_b
    const float* feat_edge = (const float*)d_in[2];
    const float* c_i       = (const float*)d_in[3];
    const float* relmask   = (const float*)d_in[4];
    const float* att_stack = (const float*)d_in[5];
    const float* stack_ptr = (const float*)d_in[6];
    const float* map_c_w   = (const float*)d_in[8];
    const float* map_c_b   = (const float*)d_in[9];
    float* out = (float*)d_out;

    query_kernel<<<B, 256>>>(c_i, map_c_w, map_c_b, att_stack, stack_ptr);
    maskpow_kernel<<<dim3(8, B), 128>>>(relmask, 0);
    maskpow_kernel<<<dim3(8, B), 128>>>(relmask, 1);
    maskpow_kernel<<<dim3(8, B), 128>>>(relmask, 2);
    main_kernel<<<B * NF, 256>>>(feat_edge);
    finalize_kernel<<<B, 256>>>(att_stack, stack_ptr, out);
}

// round 2
// speedup vs baseline: 1.1706x; 1.1706x over previous
#include <cuda_runtime.h>
#include <math.h>

#define B   32
#define NF  128
#define DE  256
#define DH  512
#define G   2
#define SL  8

// ---- device scratch (no allocations allowed) ----
__device__ float g_query[B * DE];
__device__ float g_attin[B * NF * G];
__device__ float g_bufA[B * NF * NF];
__device__ float g_bufB[B * NF * NF];
__device__ float g_final[B * NF * NF];
__device__ float g_attout[B * NF * G];

__device__ __forceinline__ void cp_async16(void* smem_dst, const void* gmem_src) {
    unsigned sa = (unsigned)__cvta_generic_to_shared(smem_dst);
    asm volatile("cp.async.ca.shared.global [%0], [%1], 16;" :: "r"(sa), "l"(gmem_src));
}

// ============================================================================
// Kernel 1: query = c_i @ W^T + b, and att_in = einsum('bngs,bs->bng')
// grid(B), block(256)
// ============================================================================
__global__ __launch_bounds__(256) void query_kernel(
    const float* __restrict__ c_i, const float* __restrict__ W,
    const float* __restrict__ bias,
    const float* __restrict__ att_stack, const float* __restrict__ stack_ptr)
{
    int b = blockIdx.x;
    int t = threadIdx.x;
    __shared__ float csh[DH];
    csh[t]       = c_i[b * DH + t];
    csh[t + 256] = c_i[b * DH + t + 256];
    __syncthreads();

    int w = t >> 5, lane = t & 31;
    for (int d = w; d < DE; d += 8) {
        const float* Wr = W + (size_t)d * DH;
        float s = 0.f;
        #pragma unroll
        for (int i = 0; i < DH / 32; i++)
            s += Wr[lane + 32 * i] * csh[lane + 32 * i];
        #pragma unroll
        for (int o = 16; o; o >>= 1) s += __shfl_xor_sync(~0u, s, o);
        if (lane == 0) g_query[b * DE + d] = s + bias[d];
    }

    {
        int n = t >> 1, g = t & 1;
        const float* as = att_stack + (((size_t)b * NF + n) * G + g) * SL;
        const float* sp = stack_ptr + b * SL;
        float s = 0.f;
        #pragma unroll
        for (int ss = 0; ss < SL; ss++) s += as[ss] * sp[ss];
        g_attin[(b * NF + n) * G + g] = s;
    }
}

// ============================================================================
// Kernel 2: mask power step with cp.async double-buffered pipeline.
// next = (cur @ M) * 0.9 ; final (+)= next
// grid(8, B), block(128). 16 output rows per block, 4x4 register tile/thread.
// ============================================================================
__global__ __launch_bounds__(128) void maskpow_kernel(
    const float* __restrict__ relmask, int step)
{
    int b  = blockIdx.y;
    int n0 = blockIdx.x * 16;
    const float* Mb = relmask + (size_t)b * NF * NF;
    const float* cb = (step == 0 ? relmask : (step == 1 ? (const float*)g_bufA
                                                        : (const float*)g_bufB))
                      + (size_t)b * NF * NF;
    float* outb = (step == 1 ? g_bufB : g_bufA) + (size_t)b * NF * NF;
    float* fin  = g_final + (size_t)b * NF * NF;

    __shared__ float csh[16][NF];
    __shared__ float msh[2][32][NF];
    int t = threadIdx.x;

    // prefetch c tile (16x128 = 8KB): 4 x 16B per thread
    {
        const float4* src = (const float4*)(cb + (size_t)n0 * NF);
        float4* dst = (float4*)&csh[0][0];
        #pragma unroll
        for (int i = 0; i < 4; i++)
            cp_async16(dst + t + 128 * i, src + t + 128 * i);
    }
    // prefetch M k-tile 0 (32x128 = 16KB): 8 x 16B per thread
    {
        const float4* src = (const float4*)Mb;
        float4* dst = (float4*)&msh[0][0][0];
        #pragma unroll
        for (int i = 0; i < 8; i++)
            cp_async16(dst + t + 128 * i, src + t + 128 * i);
    }
    asm volatile("cp.async.commit_group;");

    float acc[4][4] = {};
    int tn = (t >> 5) * 4;
    int tm = (t & 31) * 4;

    for (int kt = 0; kt < 4; kt++) {
        if (kt < 3) {
            const float4* src = (const float4*)(Mb + (size_t)(kt + 1) * 32 * NF);
            float4* dst = (float4*)&msh[(kt + 1) & 1][0][0];
            #pragma unroll
            for (int i = 0; i < 8; i++)
                cp_async16(dst + t + 128 * i, src + t + 128 * i);
            asm volatile("cp.async.commit_group;");
            asm volatile("cp.async.wait_group 1;");
        } else {
            asm volatile("cp.async.wait_group 0;");
        }
        __syncthreads();

        const float (*mb)[NF] = msh[kt & 1];
        #pragma unroll
        for (int kk4 = 0; kk4 < 8; kk4++) {
            float cva[4], cvb[4], cvc[4], cvd[4];
            *(float4*)cva = *(const float4*)&csh[tn + 0][kt * 32 + kk4 * 4];
            *(float4*)cvb = *(const float4*)&csh[tn + 1][kt * 32 + kk4 * 4];
            *(float4*)cvc = *(const float4*)&csh[tn + 2][kt * 32 + kk4 * 4];
            *(float4*)cvd = *(const float4*)&csh[tn + 3][kt * 32 + kk4 * 4];
            #pragma unroll
            for (int j = 0; j < 4; j++) {
                float4 mv = *(const float4*)&mb[kk4 * 4 + j][tm];
                acc[0][0] += cva[j] * mv.x; acc[0][1] += cva[j] * mv.y;
                acc[0][2] += cva[j] * mv.z; acc[0][3] += cva[j] * mv.w;
                acc[1][0] += cvb[j] * mv.x; acc[1][1] += cvb[j] * mv.y;
                acc[1][2] += cvb[j] * mv.z; acc[1][3] += cvb[j] * mv.w;
                acc[2][0] += cvc[j] * mv.x; acc[2][1] += cvc[j] * mv.y;
                acc[2][2] += cvc[j] * mv.z; acc[2][3] += cvc[j] * mv.w;
                acc[3][0] += cvd[j] * mv.x; acc[3][1] += cvd[j] * mv.y;
                acc[3][2] += cvd[j] * mv.z; acc[3][3] += cvd[j] * mv.w;
            }
        }
        __syncthreads();
    }

    #pragma unroll
    for (int i = 0; i < 4; i++) {
        int n = n0 + tn + i;
        size_t base = (size_t)n * NF + tm;
        float4 v;
        v.x = 0.9f * acc[i][0]; v.y = 0.9f * acc[i][1];
        v.z = 0.9f * acc[i][2]; v.w = 0.9f * acc[i][3];
        *(float4*)&outb[base] = v;
        float4 f;
        if (step == 0) {
            float4 mm = *(const float4*)&Mb[base];
            f.x = mm.x + v.x; f.y = mm.y + v.y; f.z = mm.z + v.z; f.w = mm.w + v.w;
        } else {
            float4 pf = *(const float4*)&fin[base];
            f.x = pf.x + v.x; f.y = pf.y + v.y; f.z = pf.z + v.z; f.w = pf.w + v.w;
        }
        *(float4*)&fin[base] = f;
    }
}

// ============================================================================
// Kernel 3: main stream.  Block = (b, m).  For all n:
//   weit = sigmoid(feat_edge[b,n,m,:] . query[b,:]) * final_mask[b,n,m]
//   att_out[b,m,g] += att_in[b,n,g] * weit        (block-local, no atomics)
// grid(B*NF), block(256) = 8 warps, warp handles 16 n's.
// ============================================================================
__global__ __launch_bounds__(256) void main_kernel(const float* __restrict__ fe)
{
    int bid = blockIdx.x;
    int b = bid >> 7;
    int m = bid & 127;
    __shared__ float qsh[DE];
    __shared__ float ash[NF * G];
    __shared__ float msk[NF];
    __shared__ float part[8][2];

    int t = threadIdx.x;
    qsh[t] = g_query[b * DE + t];
    ash[t] = g_attin[b * NF * G + t];
    if (t < NF) msk[t] = g_final[((size_t)b * NF + t) * NF + m];
    __syncthreads();

    int w = t >> 5, lane = t & 31;
    float4 q1 = *(const float4*)&qsh[lane * 4];
    float4 q2 = *(const float4*)&qsh[128 + lane * 4];
    const float* febase = fe + (((size_t)b * NF) * NF + m) * DE;

    float p0 = 0.f, p1 = 0.f;
    #pragma unroll 2
    for (int j = 0; j < 16; j++) {
        int n = w + 8 * j;
        float mk = msk[n];
        if (mk != 0.f) {
            const float4* row = (const float4*)(febase + (size_t)n * NF * DE);
            float4 v1 = row[lane];
            float4 v2 = row[lane + 32];
            float s = v1.x * q1.x + v1.y * q1.y + v1.z * q1.z + v1.w * q1.w
                    + v2.x * q2.x + v2.y * q2.y + v2.z * q2.z + v2.w * q2.w;
            #pragma unroll
            for (int o = 16; o; o >>= 1) s += __shfl_xor_sync(~0u, s, o);
            float wv = mk / (1.f + __expf(-s));
            p0 += ash[n * 2]     * wv;
            p1 += ash[n * 2 + 1] * wv;
        }
    }
    if (lane == 0) { part[w][0] = p0; part[w][1] = p1; }
    __syncthreads();
    if (t < 2) {
        float s = 0.f;
        #pragma unroll
        for (int i = 0; i < 8; i++) s += part[i][t];
        g_attout[((size_t)b * NF + m) * G + t] = s;
    }
}

// ============================================================================
// Kernel 4: normalize + blend + write all four outputs.
// grid(B), block(256)
// ============================================================================
__global__ __launch_bounds__(256) void finalize_kernel(
    const float* __restrict__ att_stack, const float* __restrict__ stack_ptr,
    float* __restrict__ out)
{
    int b = blockIdx.x;
    int t = threadIdx.x;
    __shared__ float att[NF * G];
    __shared__ float norm[G];
    __shared__ float sps[SL];

    att[t] = g_attout[b * NF * G + t];
    if (t < SL) sps[t] = stack_ptr[b * SL + t];
    __syncthreads();

    if (t < 64) {
        int g = t >> 5, lane = t & 31;
        float mx = -1e30f;
        for (int i = lane; i < NF; i += 32) mx = fmaxf(mx, att[i * G + g]);
        #pragma unroll
        for (int o = 16; o; o >>= 1) mx = fmaxf(mx, __shfl_xor_sync(~0u, mx, o));
        if (lane == 0) norm[g] = (mx <= 1.f) ? 1.f : mx;
    }
    __syncthreads();

    const float* asb = att_stack + (size_t)b * NF * G * SL;
    float* ob = out + (size_t)b * NF * G * SL;
    for (int idx = t; idx < NF * G * SL; idx += 256) {
        int s = idx & 7;
        int g = (idx >> 3) & 1;
        int n = idx >> 4;
        float a  = att[n * G + g] / norm[g];
        float sp = sps[s];
        ob[idx] = a * sp + asb[idx] * (1.f - sp);
    }
    if (t < SL) out[(size_t)B * NF * G * SL + b * SL + t] = sps[t];
    float* z = out + (size_t)B * NF * G * SL + (size_t)B * SL;
    for (int i = t; i < DH; i += 256) {
        z[(size_t)b * DH + i] = 0.f;
        z[(size_t)B * DH + (size_t)b * DH + i] = 0.f;
    }
}

// ============================================================================
extern "C" void kernel_launch(void* const* d_in, const int* in_sizes, int n_in,
                              void* d_out, int out_size)
{
    const float* feat_edge = (const float*)d_in[2];
    const float* c_i       = (const float*)d_in[3];
    const float* relmask   = (const float*)d_in[4];
    const float* att_stack = (const float*)d_in[5];
    const float* stack_ptr = (const float*)d_in[6];
    const float* map_c_w   = (const float*)d_in[8];
    const float* map_c_b   = (const float*)d_in[9];
    float* out = (float*)d_out;

    query_kernel<<<B, 256>>>(c_i, map_c_w, map_c_b, att_stack, stack_ptr);
    maskpow_kernel<<<dim3(8, B), 128>>>(relmask, 0);
    maskpow_kernel<<<dim3(8, B), 128>>>(relmask, 1);
    maskpow_kernel<<<dim3(8, B), 128>>>(relmask, 2);
    main_kernel<<<B * NF, 256>>>(feat_edge);
    finalize_kernel<<<B, 256>>>(att_stack, stack_ptr, out);
}